// round 2
// baseline (speedup 1.0000x reference)
#include <cuda_runtime.h>
#include <math.h>

#define N_NODES 50000
#define E_EDGES 800000
#define NFEAT   512
#define NHID    256
#define NCLASS  64

// Scratch (static __device__ arrays; no allocations allowed in kernel_launch)
__device__ float g_xw1[N_NODES * NHID];   // x @ W1
__device__ float g_h  [N_NODES * NHID];   // spmm0 accumulator (pre-relu)
__device__ float g_hw2[N_NODES * NCLASS]; // relu(h+b1) @ W2
__device__ float g_h2 [N_NODES * NCLASS]; // spmm1 accumulator

// ---------------------------------------------------------------------------
// Zero both accumulators
// ---------------------------------------------------------------------------
__global__ void zero_kernel() {
    int i = blockIdx.x * blockDim.x + threadIdx.x;
    const int t1 = N_NODES * NHID / 4;
    const int t2 = N_NODES * NCLASS / 4;
    float4 z = make_float4(0.f, 0.f, 0.f, 0.f);
    if (i < t1) ((float4*)g_h)[i] = z;
    if (i < t2) ((float4*)g_h2)[i] = z;
}

// ---------------------------------------------------------------------------
// SGEMM 128x128x8, 256 threads, 8x8 micro-tile. C = A(MxK) * B(KxN), N=256.
// ---------------------------------------------------------------------------
__global__ __launch_bounds__(256) void sgemm_128x128(
    const float* __restrict__ A, const float* __restrict__ B,
    float* __restrict__ C, int M, int Nc, int K)
{
    __shared__ float As[8][128];
    __shared__ float Bs[8][128];
    const int tid = threadIdx.x;
    const int blockRow = blockIdx.y;
    const int blockCol = blockIdx.x;

    const int rowA = tid >> 1;           // 0..127
    const int colA = (tid & 1) * 4;      // 0 or 4
    const int rowB = tid >> 5;           // 0..7
    const int colB = (tid & 31) * 4;     // 0..124

    const int tRow = (tid >> 4) * 8;     // 0..120
    const int tCol = (tid & 15) * 8;     // 0..120

    float acc[8][8];
    #pragma unroll
    for (int i = 0; i < 8; i++)
        #pragma unroll
        for (int j = 0; j < 8; j++) acc[i][j] = 0.f;

    const int gRowA = blockRow * 128 + rowA;
    const float* Aptr = A + (long)gRowA * K;
    const float* Bptr = B + blockCol * 128;

    for (int k0 = 0; k0 < K; k0 += 8) {
        float4 av;
        if (gRowA < M) av = *(const float4*)(Aptr + k0 + colA);
        else           av = make_float4(0.f, 0.f, 0.f, 0.f);
        As[colA + 0][rowA] = av.x;
        As[colA + 1][rowA] = av.y;
        As[colA + 2][rowA] = av.z;
        As[colA + 3][rowA] = av.w;

        float4 bv = *(const float4*)(Bptr + (long)(k0 + rowB) * Nc + colB);
        *(float4*)&Bs[rowB][colB] = bv;
        __syncthreads();

        #pragma unroll
        for (int kk = 0; kk < 8; kk++) {
            float ra[8], rb[8];
            #pragma unroll
            for (int i = 0; i < 8; i++) ra[i] = As[kk][tRow + i];
            #pragma unroll
            for (int j = 0; j < 8; j++) rb[j] = Bs[kk][tCol + j];
            #pragma unroll
            for (int i = 0; i < 8; i++)
                #pragma unroll
                for (int j = 0; j < 8; j++)
                    acc[i][j] += ra[i] * rb[j];
        }
        __syncthreads();
    }

    #pragma unroll
    for (int i = 0; i < 8; i++) {
        int r = blockRow * 128 + tRow + i;
        if (r < M) {
            float* cp = C + (long)r * Nc + blockCol * 128 + tCol;
            *(float4*)(cp)     = make_float4(acc[i][0], acc[i][1], acc[i][2], acc[i][3]);
            *(float4*)(cp + 4) = make_float4(acc[i][4], acc[i][5], acc[i][6], acc[i][7]);
        }
    }
}

// ---------------------------------------------------------------------------
// SGEMM 128x64x8 with fused A-side relu(a + b1). C = relu(A+b1) @ B, N=64.
// A is g_h (pre-activation accumulator), b1 broadcast over rows.
// ---------------------------------------------------------------------------
__global__ __launch_bounds__(256) void sgemm_128x64_relu(
    const float* __restrict__ A, const float* __restrict__ b1,
    const float* __restrict__ B, float* __restrict__ C,
    int M, int Nc, int K)
{
    __shared__ float As[8][128];
    __shared__ float Bs[8][64];
    const int tid = threadIdx.x;
    const int blockRow = blockIdx.y;

    const int rowA = tid >> 1;
    const int colA = (tid & 1) * 4;

    const int tRow = (tid >> 4) * 8;    // 0..120
    const int tCol = (tid & 15) * 4;    // 0..60

    float acc[8][4];
    #pragma unroll
    for (int i = 0; i < 8; i++)
        #pragma unroll
        for (int j = 0; j < 4; j++) acc[i][j] = 0.f;

    const int gRowA = blockRow * 128 + rowA;
    const float* Aptr = A + (long)gRowA * K;

    for (int k0 = 0; k0 < K; k0 += 8) {
        float4 av, bb;
        if (gRowA < M) {
            av = *(const float4*)(Aptr + k0 + colA);
            bb = *(const float4*)(b1 + k0 + colA);
            av.x = fmaxf(av.x + bb.x, 0.f);
            av.y = fmaxf(av.y + bb.y, 0.f);
            av.z = fmaxf(av.z + bb.z, 0.f);
            av.w = fmaxf(av.w + bb.w, 0.f);
        } else {
            av = make_float4(0.f, 0.f, 0.f, 0.f);
        }
        As[colA + 0][rowA] = av.x;
        As[colA + 1][rowA] = av.y;
        As[colA + 2][rowA] = av.z;
        As[colA + 3][rowA] = av.w;

        if (tid < 128) {
            int rowB = tid >> 4;          // 0..7
            int colB = (tid & 15) * 4;    // 0..60
            float4 bv = *(const float4*)(B + (long)(k0 + rowB) * Nc + colB);
            *(float4*)&Bs[rowB][colB] = bv;
        }
        __syncthreads();

        #pragma unroll
        for (int kk = 0; kk < 8; kk++) {
            float ra[8], rb[4];
            #pragma unroll
            for (int i = 0; i < 8; i++) ra[i] = As[kk][tRow + i];
            #pragma unroll
            for (int j = 0; j < 4; j++) rb[j] = Bs[kk][tCol + j];
            #pragma unroll
            for (int i = 0; i < 8; i++)
                #pragma unroll
                for (int j = 0; j < 4; j++)
                    acc[i][j] += ra[i] * rb[j];
        }
        __syncthreads();
    }

    #pragma unroll
    for (int i = 0; i < 8; i++) {
        int r = blockRow * 128 + tRow + i;
        if (r < M) {
            *(float4*)(C + (long)r * Nc + tCol) =
                make_float4(acc[i][0], acc[i][1], acc[i][2], acc[i][3]);
        }
    }
}

// ---------------------------------------------------------------------------
// SPMM over NHID=256 features: warp per edge, red.global.add.v4.f32 scatter
// ---------------------------------------------------------------------------
__device__ __forceinline__ void red_add_v4(float4* ptr, float4 v) {
    asm volatile("red.global.add.v4.f32 [%0], {%1,%2,%3,%4};"
                 :: "l"(ptr), "f"(v.x), "f"(v.y), "f"(v.z), "f"(v.w)
                 : "memory");
}

__global__ __launch_bounds__(256) void spmm_nhid(
    const int* __restrict__ row, const int* __restrict__ col,
    const float* __restrict__ val)
{
    int e = blockIdx.x * (blockDim.x >> 5) + (threadIdx.x >> 5);
    if (e >= E_EDGES) return;
    int lane = threadIdx.x & 31;
    int c = col[e];
    int r = row[e];
    float v = val[e];
    const float4* s = (const float4*)(g_xw1 + (long)c * NHID);
    float4*       d = (float4*)(g_h   + (long)r * NHID);
    #pragma unroll
    for (int j = 0; j < 2; j++) {
        float4 x = s[lane + 32 * j];
        x.x *= v; x.y *= v; x.z *= v; x.w *= v;
        red_add_v4(d + lane + 32 * j, x);
    }
}

// ---------------------------------------------------------------------------
// SPMM over NCLASS=64 features: 16 threads per edge
// ---------------------------------------------------------------------------
__global__ __launch_bounds__(256) void spmm_ncls(
    const int* __restrict__ row, const int* __restrict__ col,
    const float* __restrict__ val)
{
    long t = (long)blockIdx.x * blockDim.x + threadIdx.x;
    int e = (int)(t >> 4);
    if (e >= E_EDGES) return;
    int l = (int)(t & 15);
    int c = col[e];
    int r = row[e];
    float v = val[e];
    const float4* s = (const float4*)(g_hw2 + (long)c * NCLASS);
    float4*       d = (float4*)(g_h2  + (long)r * NCLASS);
    float4 x = s[l];
    x.x *= v; x.y *= v; x.z *= v; x.w *= v;
    red_add_v4(d + l, x);
}

// ---------------------------------------------------------------------------
// Final: logits = (h2 + b2) @ LW + Lb ; log_softmax. One warp per node.
// ---------------------------------------------------------------------------
__global__ __launch_bounds__(256) void final_kernel(
    const float* __restrict__ b2, const float* __restrict__ LW,
    const float* __restrict__ Lb, float* __restrict__ out)
{
    __shared__ float sLW[NCLASS * NCLASS];  // [k][c], 16KB
    __shared__ float sh2[8][NCLASS];
    const int tid = threadIdx.x;
    for (int i = tid; i < NCLASS * NCLASS; i += 256) sLW[i] = LW[i];

    const int warp = tid >> 5;
    const int lane = tid & 31;
    const int node = blockIdx.x * 8 + warp;

    if (node < N_NODES) {
        sh2[warp][lane]      = g_h2[(long)node * NCLASS + lane]      + b2[lane];
        sh2[warp][lane + 32] = g_h2[(long)node * NCLASS + lane + 32] + b2[lane + 32];
    }
    __syncthreads();
    if (node >= N_NODES) return;

    float l0 = Lb[lane];
    float l1 = Lb[lane + 32];
    #pragma unroll
    for (int k = 0; k < NCLASS; k++) {
        float hv = sh2[warp][k];
        l0 += hv * sLW[k * NCLASS + lane];
        l1 += hv * sLW[k * NCLASS + lane + 32];
    }

    float m = fmaxf(l0, l1);
    #pragma unroll
    for (int off = 16; off; off >>= 1)
        m = fmaxf(m, __shfl_xor_sync(0xffffffff, m, off));
    float s = expf(l0 - m) + expf(l1 - m);
    #pragma unroll
    for (int off = 16; off; off >>= 1)
        s += __shfl_xor_sync(0xffffffff, s, off);
    float lse = m + logf(s);

    out[(long)node * NCLASS + lane]      = l0 - lse;
    out[(long)node * NCLASS + lane + 32] = l1 - lse;
}

// ---------------------------------------------------------------------------
// Launch
// ---------------------------------------------------------------------------
extern "C" void kernel_launch(void* const* d_in, const int* in_sizes, int n_in,
                              void* d_out, int out_size)
{
    const float* x   = (const float*)d_in[0];
    const float* a0v = (const float*)d_in[1];
    const float* a1v = (const float*)d_in[2];
    const float* W1  = (const float*)d_in[3];
    const float* b1  = (const float*)d_in[4];
    const float* W2  = (const float*)d_in[5];
    const float* b2  = (const float*)d_in[6];
    const float* LW  = (const float*)d_in[7];
    const float* Lb  = (const float*)d_in[8];
    const int*   a0r = (const int*)d_in[9];
    const int*   a0c = (const int*)d_in[10];
    const int*   a1r = (const int*)d_in[11];
    const int*   a1c = (const int*)d_in[12];
    float* out = (float*)d_out;

    float *p_xw1, *p_h, *p_hw2;
    cudaGetSymbolAddress((void**)&p_xw1, g_xw1);
    cudaGetSymbolAddress((void**)&p_h,   g_h);
    cudaGetSymbolAddress((void**)&p_hw2, g_hw2);

    // Zero accumulators (covers both g_h and g_h2)
    {
        int threads = N_NODES * NHID / 4;
        zero_kernel<<<(threads + 255) / 256, 256>>>();
    }

    // GEMM1: g_xw1 = x @ W1  (50000x512 * 512x256)
    {
        dim3 grid(NHID / 128, (N_NODES + 127) / 128);
        sgemm_128x128<<<grid, 256>>>(x, W1, p_xw1, N_NODES, NHID, NFEAT);
    }

    // SPMM0: g_h += adj0 * g_xw1   (warp per edge)
    {
        int blocks = (E_EDGES + 7) / 8;
        spmm_nhid<<<blocks, 256>>>(a0r, a0c, a0v);
    }

    // GEMM2 (fused relu+bias on A): g_hw2 = relu(g_h + b1) @ W2
    {
        dim3 grid(1, (N_NODES + 127) / 128);
        sgemm_128x64_relu<<<grid, 256>>>(p_h, b1, W2, p_hw2, N_NODES, NCLASS, NHID);
    }

    // SPMM1: g_h2 += adj1 * g_hw2   (16 threads per edge)
    {
        long threads = (long)E_EDGES * 16;
        spmm_ncls<<<(int)((threads + 255) / 256), 256>>>(a1r, a1c, a1v);
    }

    // Final linear + log_softmax
    {
        final_kernel<<<(N_NODES + 7) / 8, 256>>>(b2, LW, Lb, out);
    }
}